// round 13
// baseline (speedup 1.0000x reference)
#include <cuda_runtime.h>
#include <cuda_fp16.h>
#include <cstdint>
#include <cstddef>

// ---------------- problem constants ----------------
#define B_   16
#define P_   512
#define MS_  13
#define D_   768
#define LH_  144
#define K_   9216
#define BP_  8192

// ---------------- GEMM tiling: 4 warps, m64n64 warp tiles ----------------
#define BM   128
#define BN   128
#define BK   64
#define NKT  144
#define NTHREADS 128

// smem: 3-stage A (128x64 fp16, swizzled) + 3-stage W (2x 64x64-half)
#define AST  16384
#define WST  16384
#define OFF_A 0
#define OFF_W (3 * AST)                 // 49152
#define SMEM_BYTES (6 * 16384)          // 98304 -> 2 CTAs/SM
#define FT_STRIDE 132                   // fp32 epilogue tile stride (16B-aligned rows)

__device__ __half g_Ah[(size_t)BP_ * K_];   // masked A, fp16
__device__ __half g_Wh[(size_t)K_ * D_];    // W_O, fp16
__device__ float  g_cbase[B_ * D_];

#define DEVI __device__ __forceinline__

DEVI uint32_t smem_u32(const void* p) {
    uint32_t a;
    asm("{ .reg .u64 t; cvta.to.shared.u64 t, %1; cvt.u32.u64 %0, t; }"
        : "=r"(a) : "l"(p));
    return a;
}
DEVI uint32_t swz(uint32_t off) { return off ^ ((off >> 3) & 0x70); }

DEVI void cp16(uint32_t dst, const void* src) {
    asm volatile("cp.async.cg.shared.global [%0], [%1], 16;" :: "r"(dst), "l"(src));
}
DEVI void cp_commit() { asm volatile("cp.async.commit_group;" ::: "memory"); }
DEVI void cp_wait1()  { asm volatile("cp.async.wait_group 1;" ::: "memory"); }
DEVI void cp_wait0()  { asm volatile("cp.async.wait_group 0;" ::: "memory"); }

DEVI uint32_t packh(float lo, float hi) {
    uint32_t r;
    asm("cvt.rn.f16x2.f32 %0, %1, %2;" : "=r"(r) : "f"(hi), "f"(lo));
    return r;
}
DEVI void ldsm4(uint32_t* r, uint32_t addr) {
    asm volatile("ldmatrix.sync.aligned.m8n8.x4.shared.b16 {%0,%1,%2,%3}, [%4];"
                 : "=r"(r[0]), "=r"(r[1]), "=r"(r[2]), "=r"(r[3]) : "r"(addr));
}
DEVI void ldsm4t(uint32_t* r, uint32_t addr) {
    asm volatile("ldmatrix.sync.aligned.m8n8.x4.trans.shared.b16 {%0,%1,%2,%3}, [%4];"
                 : "=r"(r[0]), "=r"(r[1]), "=r"(r[2]), "=r"(r[3]) : "r"(addr));
}
DEVI void mma16(float* d, const uint32_t* a, uint32_t b0, uint32_t b1) {
    asm volatile(
        "mma.sync.aligned.m16n8k16.row.col.f32.f16.f16.f32 "
        "{%0,%1,%2,%3},{%4,%5,%6,%7},{%8,%9},{%0,%1,%2,%3};"
        : "+f"(d[0]), "+f"(d[1]), "+f"(d[2]), "+f"(d[3])
        : "r"(a[0]), "r"(a[1]), "r"(a[2]), "r"(a[3]), "r"(b0), "r"(b1));
}

// ---------------- prep: A*mask -> fp16 (DRAM-bound) ----------------
__global__ void __launch_bounds__(256)
acvt_kernel(const float* __restrict__ A, const float* __restrict__ attn_mask) {
    const int i = blockIdx.x * 256 + threadIdx.x;    // over BP*K/8
    const int row = i / (K_ / 8);
    const int k = (i % (K_ / 8)) * 8;
    const int b = row >> 9;
    const float s = __ldg(attn_mask + b * LH_ + (k >> 6));
    const float* p = A + (size_t)row * K_ + k;
    const float4 v0 = *(const float4*)p;
    const float4 v1 = *(const float4*)(p + 4);
    uint4 h;
    h.x = packh(v0.x * s, v0.y * s);
    h.y = packh(v0.z * s, v0.w * s);
    h.z = packh(v1.x * s, v1.y * s);
    h.w = packh(v1.z * s, v1.w * s);
    ((uint4*)g_Ah)[i] = h;
}

// ---------------- prep: W -> fp16 ----------------
__global__ void __launch_bounds__(256) wcvt_kernel(const float* __restrict__ W) {
    const int i = blockIdx.x * 256 + threadIdx.x;
    const float4 v = ((const float4*)W)[i];
    uint2 h;
    h.x = packh(v.x, v.y);
    h.y = packh(v.z, v.w);
    ((uint2*)g_Wh)[i] = h;
}

// ---------------- prep: per-(b,d) constant term ----------------
__global__ void __launch_bounds__(256)
cbase_kernel(const float* __restrict__ mlp_mask,
             const float* __restrict__ attn_mask,
             const float* __restrict__ mlp_const,
             const float* __restrict__ attn_const,
             const float* __restrict__ post_bias) {
    __shared__ float red[4][64];
    const int tid = threadIdx.x;
    const int dl = tid & 63, g = tid >> 6;
    const int d = blockIdx.x * 64 + dl;
    const int b = blockIdx.y;
    float acc = 0.f;
#pragma unroll 4
    for (int lh = g * 36; lh < (g + 1) * 36; lh++)
        acc += (1.0f - attn_mask[b * LH_ + lh]) * attn_const[lh * D_ + d];
    if (g == 0) {
        acc += post_bias[d];
#pragma unroll
        for (int m = 0; m < MS_; m++)
            acc += (1.0f - mlp_mask[b * MS_ + m]) * mlp_const[m * D_ + d];
    }
    red[g][dl] = acc;
    __syncthreads();
    if (g == 0)
        g_cbase[b * D_ + d] = (red[0][dl] + red[1][dl]) + (red[2][dl] + red[3][dl]);
}

// ---------------- GEMM (m64n64 warps, ks-pipelined frags) ----------------
// chunk j (j=0..3): 1/4 of A tile + 1/4 of W tile (2 A cp + 2 W cp per thread)
DEVI void issue_chunk(uint32_t smb, const __half* Abase, const __half* Wbase,
                      int kt, int st, int tid, int j) {
    const uint32_t sa = smb + OFF_A + (uint32_t)st * AST;
    const __half* ag = Abase + kt * BK;
    const uint32_t sw = smb + OFF_W + (uint32_t)st * WST;
    const __half* wg = Wbase + (size_t)kt * BK * D_;
#pragma unroll
    for (int jj = 0; jj < 2; jj++) {
        const int i = tid + 128 * (2 * j + jj);
        {   // A: 1024 cp total, r=i>>3 c=i&7
            const int r = i >> 3, c = i & 7;
            cp16(sa + swz((uint32_t)r * 128 + c * 16), ag + (size_t)r * K_ + c * 8);
        }
        {   // W: 1024 cp total, r=i>>4 ch=i&15
            const int r = i >> 4, c = i & 15;
            cp16(sw + (uint32_t)(c >> 3) * 8192 + swz((uint32_t)r * 128 + (c & 7) * 16),
                 wg + (size_t)r * D_ + c * 8);
        }
    }
}

__global__ void __launch_bounds__(NTHREADS, 2)
gemm_kernel(const float* __restrict__ mlp_cache,
            const float* __restrict__ mlp_mask,
            float* __restrict__ out) {
    extern __shared__ char smem[];
    const uint32_t smb = smem_u32(smem);
    const int tid = threadIdx.x;
    const int wid = tid >> 5, lane = tid & 31;
    const int ntile = blockIdx.x, mtile = blockIdx.y;
    const int b = mtile >> 2;
    const int row0 = mtile * BM, n0 = ntile * BN;
    const __half* Abase = g_Ah + (size_t)row0 * K_;
    const __half* Wbase = g_Wh + n0;

    const int wm = (wid & 1) * 64;                      // warp m offset (0/64)
    const uint32_t wqoff = (uint32_t)(wid >> 1) * 8192; // warp n half (0/64)

    // prologue: stages 0,1 fully
#pragma unroll
    for (int j = 0; j < 4; j++) issue_chunk(smb, Abase, Wbase, 0, 0, tid, j);
    cp_commit();
#pragma unroll
    for (int j = 0; j < 4; j++) issue_chunk(smb, Abase, Wbase, 1, 1, tid, j);
    cp_commit();

    float acc[4][8][4];
#pragma unroll
    for (int i = 0; i < 4; i++)
#pragma unroll
        for (int j = 0; j < 8; j++)
#pragma unroll
            for (int k = 0; k < 4; k++) acc[i][j][k] = 0.0f;

    const uint32_t a_lrow = (uint32_t)(lane & 15) * 128 + (uint32_t)(lane >> 4) * 16;
    const uint32_t w_lrow = a_lrow;     // same lane pattern for ldsm4t

    int st = 0;
    for (int kt = 0; kt < NKT; ++kt) {
        cp_wait1();
        __syncthreads();
        int st2 = st + 2; if (st2 >= 3) st2 -= 3;
        const bool pf = (kt + 2 < NKT);

        const uint32_t aA = smb + OFF_A + (uint32_t)st * AST;
        const uint32_t wB = smb + OFF_W + (uint32_t)st * WST + wqoff;
        if (++st == 3) st = 0;

        uint32_t af[2][4][4], tb[2][4][4];
        // preload ks=0 fragments
#pragma unroll
        for (int im = 0; im < 4; im++)
            ldsm4(af[0][im], aA + swz((uint32_t)(wm + im * 16) * 128 + a_lrow));
#pragma unroll
        for (int n2 = 0; n2 < 4; n2++)
            ldsm4t(tb[0][n2], wB + swz(w_lrow + n2 * 32));

#pragma unroll
        for (int ks = 0; ks < 4; ks++) {
            const int cur = ks & 1, nxt = cur ^ 1;
            if (ks < 3) {   // prefetch ks+1 fragments (overlaps mma train)
#pragma unroll
                for (int im = 0; im < 4; im++)
                    ldsm4(af[nxt][im], aA + swz((uint32_t)(wm + im * 16) * 128
                                                + (ks + 1) * 32 + a_lrow));
#pragma unroll
                for (int n2 = 0; n2 < 4; n2++)
                    ldsm4t(tb[nxt][n2], wB + swz(((uint32_t)(ks + 1) * 16) * 128
                                                 + w_lrow + n2 * 32));
            }
            if (pf) issue_chunk(smb, Abase, Wbase, kt + 2, st2, tid, ks);
#pragma unroll
            for (int n2 = 0; n2 < 4; n2++)
#pragma unroll
                for (int im = 0; im < 4; im++) {
                    mma16(acc[im][2 * n2],     af[cur][im], tb[cur][n2][0], tb[cur][n2][1]);
                    mma16(acc[im][2 * n2 + 1], af[cur][im], tb[cur][n2][2], tb[cur][n2][3]);
                }
        }
        cp_commit();
    }

    // ---------- fused epilogue: acc -> smem, then + mlp term + cbase -> out --
    cp_wait0();
    __syncthreads();                       // all frag reads done; reuse smem
    float* ftile = (float*)smem;           // 128 x FT_STRIDE fp32

    const int wn = (wid >> 1) * 64;
    const int r0l = wm + (lane >> 2);
    const int c0l = wn + (lane & 3) * 2;
#pragma unroll
    for (int im = 0; im < 4; im++) {
        const int r = r0l + im * 16;
#pragma unroll
        for (int nb = 0; nb < 8; nb++) {
            const int c = c0l + nb * 8;
            float2* q0 = (float2*)&ftile[r * FT_STRIDE + c];
            float2* q1 = (float2*)&ftile[(r + 8) * FT_STRIDE + c];
            *q0 = make_float2(acc[im][nb][0], acc[im][nb][1]);
            *q1 = make_float2(acc[im][nb][2], acc[im][nb][3]);
        }
    }
    __syncthreads();

    float mm[MS_];
#pragma unroll
    for (int m = 0; m < MS_; m++) mm[m] = __ldg(mlp_mask + b * MS_ + m);

    // 128 rows x 32 float4-cols, 128 threads -> 32 iters
#pragma unroll 2
    for (int i = tid; i < BM * (BN / 4); i += NTHREADS) {
        const int r = i >> 5;
        const int c = (i & 31) * 4;
        float4 v = *(const float4*)&ftile[r * FT_STRIDE + c];
        const float4 cb = *(const float4*)(&g_cbase[b * D_ + n0 + c]);
        v.x += cb.x; v.y += cb.y; v.z += cb.z; v.w += cb.w;
        const float* src = mlp_cache + (size_t)(row0 + r) * MS_ * D_ + n0 + c;
#pragma unroll
        for (int m = 0; m < MS_; m++) {
            const float4 u = *(const float4*)(src + (size_t)m * D_);
            v.x += mm[m] * u.x; v.y += mm[m] * u.y;
            v.z += mm[m] * u.z; v.w += mm[m] * u.w;
        }
        *(float4*)(out + (size_t)(row0 + r) * D_ + n0 + c) = v;
    }
}

// ---------------- launch ----------------
extern "C" void kernel_launch(void* const* d_in, const int* in_sizes, int n_in,
                              void* d_out, int out_size) {
    const float* mlp_cache  = (const float*)d_in[0];
    const float* attn_cache = (const float*)d_in[1];
    const float* mlp_mask   = (const float*)d_in[2];
    const float* attn_mask  = (const float*)d_in[3];
    const float* mlp_const  = (const float*)d_in[4];
    const float* attn_const = (const float*)d_in[5];
    const float* W_O        = (const float*)d_in[6];
    const float* post_bias  = (const float*)d_in[7];
    float* out = (float*)d_out;

    cudaFuncSetAttribute(gemm_kernel, cudaFuncAttributeMaxDynamicSharedMemorySize, SMEM_BYTES);

    acvt_kernel<<<BP_ * K_ / 8 / 256, 256>>>(attn_cache, attn_mask);
    wcvt_kernel<<<K_ * D_ / 4 / 256, 256>>>(W_O);
    cbase_kernel<<<dim3(D_ / 64, B_), 256>>>(mlp_mask, attn_mask, mlp_const,
                                             attn_const, post_bias);
    gemm_kernel<<<dim3(D_ / BN, BP_ / BM), NTHREADS, SMEM_BYTES>>>(mlp_cache,
                                                                   mlp_mask, out);
}

// round 14
// speedup vs baseline: 1.0320x; 1.0320x over previous
#include <cuda_runtime.h>
#include <cuda_fp16.h>
#include <cstdint>
#include <cstddef>

// ---------------- problem constants ----------------
#define B_   16
#define P_   512
#define MS_  13
#define D_   768
#define LH_  144
#define K_   9216
#define BP_  8192

// ---------------- GEMM tiling (R12 core) ----------------
#define BM   128
#define BN   128
#define BK   64
#define NKT  144
#define NTHREADS 256

// smem: 3-stage A (128x64 fp16, swizzled) + 3-stage W (2x 64x64-half)
#define AST  16384
#define WST  16384
#define OFF_A 0
#define OFF_W (3 * AST)                 // 49152
#define SMEM_BYTES (6 * 16384)          // 98304 -> 2 CTAs/SM
#define FT_STRIDE 132                   // fp32 epilogue tile stride (16B-aligned rows)

// merged prep grid split
#define NA_BLK (BP_ * K_ / 8 / 256)     // acvt blocks
#define NW_BLK (K_ * D_ / 4 / 256)      // wcvt blocks
#define NC_BLK ((D_ / 64) * B_)         // cbase blocks

__device__ __half g_Ah[(size_t)BP_ * K_];   // masked A, fp16
__device__ __half g_Wh[(size_t)K_ * D_];    // W_O, fp16
__device__ float  g_cbase[B_ * D_];

#define DEVI __device__ __forceinline__

DEVI uint32_t smem_u32(const void* p) {
    uint32_t a;
    asm("{ .reg .u64 t; cvta.to.shared.u64 t, %1; cvt.u32.u64 %0, t; }"
        : "=r"(a) : "l"(p));
    return a;
}
DEVI uint32_t swz(uint32_t off) { return off ^ ((off >> 3) & 0x70); }

DEVI void cp16(uint32_t dst, const void* src) {
    asm volatile("cp.async.cg.shared.global [%0], [%1], 16;" :: "r"(dst), "l"(src));
}
DEVI void cp_commit() { asm volatile("cp.async.commit_group;" ::: "memory"); }
DEVI void cp_wait1()  { asm volatile("cp.async.wait_group 1;" ::: "memory"); }
DEVI void cp_wait0()  { asm volatile("cp.async.wait_group 0;" ::: "memory"); }

DEVI uint32_t packh(float lo, float hi) {
    uint32_t r;
    asm("cvt.rn.f16x2.f32 %0, %1, %2;" : "=r"(r) : "f"(hi), "f"(lo));
    return r;
}
DEVI void ldsm4(uint32_t* r, uint32_t addr) {
    asm volatile("ldmatrix.sync.aligned.m8n8.x4.shared.b16 {%0,%1,%2,%3}, [%4];"
                 : "=r"(r[0]), "=r"(r[1]), "=r"(r[2]), "=r"(r[3]) : "r"(addr));
}
DEVI void ldsm4t(uint32_t* r, uint32_t addr) {
    asm volatile("ldmatrix.sync.aligned.m8n8.x4.trans.shared.b16 {%0,%1,%2,%3}, [%4];"
                 : "=r"(r[0]), "=r"(r[1]), "=r"(r[2]), "=r"(r[3]) : "r"(addr));
}
DEVI void mma16(float* d, const uint32_t* a, uint32_t b0, uint32_t b1) {
    asm volatile(
        "mma.sync.aligned.m16n8k16.row.col.f32.f16.f16.f32 "
        "{%0,%1,%2,%3},{%4,%5,%6,%7},{%8,%9},{%0,%1,%2,%3};"
        : "+f"(d[0]), "+f"(d[1]), "+f"(d[2]), "+f"(d[3])
        : "r"(a[0]), "r"(a[1]), "r"(a[2]), "r"(a[3]), "r"(b0), "r"(b1));
}

// ---------------- merged prep: acvt + wcvt + cbase in ONE launch ----------
__global__ void __launch_bounds__(256)
prep_kernel(const float* __restrict__ A, const float* __restrict__ attn_mask,
            const float* __restrict__ W,
            const float* __restrict__ mlp_mask,
            const float* __restrict__ mlp_const,
            const float* __restrict__ attn_const,
            const float* __restrict__ post_bias) {
    __shared__ float red[4][64];
    const int bx = blockIdx.x;
    const int tid = threadIdx.x;

    if (bx < NA_BLK) {
        // ---- acvt: A*mask -> fp16 ----
        const int i = bx * 256 + tid;                 // over BP*K/8
        const int row = i / (K_ / 8);
        const int k = (i % (K_ / 8)) * 8;
        const int b = row >> 9;
        const float s = __ldg(attn_mask + b * LH_ + (k >> 6));
        const float* p = A + (size_t)row * K_ + k;
        const float4 v0 = *(const float4*)p;
        const float4 v1 = *(const float4*)(p + 4);
        uint4 h;
        h.x = packh(v0.x * s, v0.y * s);
        h.y = packh(v0.z * s, v0.w * s);
        h.z = packh(v1.x * s, v1.y * s);
        h.w = packh(v1.z * s, v1.w * s);
        ((uint4*)g_Ah)[i] = h;
    } else if (bx < NA_BLK + NW_BLK) {
        // ---- wcvt: W -> fp16 ----
        const int i = (bx - NA_BLK) * 256 + tid;
        const float4 v = ((const float4*)W)[i];
        uint2 h;
        h.x = packh(v.x, v.y);
        h.y = packh(v.z, v.w);
        ((uint2*)g_Wh)[i] = h;
    } else {
        // ---- cbase: per-(b,d) constant term ----
        const int bb = bx - NA_BLK - NW_BLK;          // 0..NC_BLK-1
        const int dblk = bb % (D_ / 64);
        const int b = bb / (D_ / 64);
        const int dl = tid & 63, g = tid >> 6;
        const int d = dblk * 64 + dl;
        float acc = 0.f;
#pragma unroll 4
        for (int lh = g * 36; lh < (g + 1) * 36; lh++)
            acc += (1.0f - attn_mask[b * LH_ + lh]) * attn_const[lh * D_ + d];
        if (g == 0) {
            acc += post_bias[d];
#pragma unroll
            for (int m = 0; m < MS_; m++)
                acc += (1.0f - mlp_mask[b * MS_ + m]) * mlp_const[m * D_ + d];
        }
        red[g][dl] = acc;
        __syncthreads();
        if (g == 0)
            g_cbase[b * D_ + d] = (red[0][dl] + red[1][dl]) + (red[2][dl] + red[3][dl]);
    }
}

// ---------------- GEMM (R12 + epilogue L2 prefetch) ----------------
// chunk j (j=0..3): 1/4 of the A tile rows + 1/4 of the W tile rows
DEVI void issue_chunk(uint32_t smb, const __half* Abase, const __half* Wbase,
                      int kt, int st, int tid, int j) {
    const uint32_t sa = smb + OFF_A + (uint32_t)st * AST;
    const __half* ag = Abase + kt * BK;
    {
        const int i = tid + 256 * j;
        const int r = i >> 3, c = i & 7;
        cp16(sa + swz((uint32_t)r * 128 + c * 16), ag + (size_t)r * K_ + c * 8);
    }
    const uint32_t sw = smb + OFF_W + (uint32_t)st * WST;
    const __half* wg = Wbase + (size_t)kt * BK * D_;
    {
        const int i = tid + 256 * j;
        const int r = i >> 4, c = i & 15;
        cp16(sw + (uint32_t)(c >> 3) * 8192 + swz((uint32_t)r * 128 + (c & 7) * 16),
             wg + (size_t)r * D_ + c * 8);
    }
}

__global__ void __launch_bounds__(NTHREADS, 2)
gemm_kernel(const float* __restrict__ mlp_cache,
            const float* __restrict__ mlp_mask,
            float* __restrict__ out) {
    extern __shared__ char smem[];
    const uint32_t smb = smem_u32(smem);
    const int tid = threadIdx.x;
    const int wid = tid >> 5, lane = tid & 31;
    const int ntile = blockIdx.x, mtile = blockIdx.y;
    const int b = mtile >> 2;
    const int row0 = mtile * BM, n0 = ntile * BN;
    const __half* Abase = g_Ah + (size_t)row0 * K_;
    const __half* Wbase = g_Wh + n0;

    const int wm = (wid & 3) * 32;
    const uint32_t whalf = (uint32_t)(wid >> 2) * 8192;     // n half (0/64)

    // prologue: stages 0,1 fully
#pragma unroll
    for (int j = 0; j < 4; j++) issue_chunk(smb, Abase, Wbase, 0, 0, tid, j);
    cp_commit();
#pragma unroll
    for (int j = 0; j < 4; j++) issue_chunk(smb, Abase, Wbase, 1, 1, tid, j);
    cp_commit();

    float acc[2][8][4];
#pragma unroll
    for (int i = 0; i < 2; i++)
#pragma unroll
        for (int j = 0; j < 8; j++)
#pragma unroll
            for (int k = 0; k < 4; k++) acc[i][j][k] = 0.0f;

    int st = 0;
    for (int kt = 0; kt < NKT; ++kt) {
        cp_wait1();
        __syncthreads();
        int st2 = st + 2; if (st2 >= 3) st2 -= 3;
        const bool pf = (kt + 2 < NKT);

        const uint32_t aA = smb + OFF_A + (uint32_t)st * AST;
        const uint32_t wB = smb + OFF_W + (uint32_t)st * WST + whalf;
        if (++st == 3) st = 0;

#pragma unroll
        for (int ks = 0; ks < 4; ks++) {
            uint32_t af[2][4];
#pragma unroll
            for (int im = 0; im < 2; im++)
                ldsm4(af[im], aA + swz((uint32_t)(wm + im * 16 + (lane & 15)) * 128
                                       + ks * 32 + (lane >> 4) * 16));
#pragma unroll
            for (int n2 = 0; n2 < 4; n2++) {
                uint32_t t[4];
                ldsm4t(t, wB + swz((uint32_t)(ks * 16 + (lane & 15)) * 128
                                   + n2 * 32 + (lane >> 4) * 16));
                mma16(acc[0][2 * n2],     af[0], t[0], t[1]);
                mma16(acc[0][2 * n2 + 1], af[0], t[2], t[3]);
                mma16(acc[1][2 * n2],     af[1], t[0], t[1]);
                mma16(acc[1][2 * n2 + 1], af[1], t[2], t[3]);
            }
            // interleave 1/4 of next-next stage's loads behind this ks's mma train
            if (pf) issue_chunk(smb, Abase, Wbase, kt + 2, st2, tid, ks);
        }
        cp_commit();

        // L2-prefetch the epilogue's mlp_cache slice in the last 26 k-iters.
        // 851KB/CTA = 6656 x 128B lines; 1 line/thread/kt.
        const int pfi = kt - (NKT - 26);
        if (pfi >= 0) {
            const int li = pfi * NTHREADS + tid;        // < 6656
            const int seg = li >> 2, w4 = li & 3;       // 512B segment + 128B line
            const int r = seg / MS_, m = seg - r * MS_;
            const float* pa = mlp_cache + (size_t)(row0 + r) * MS_ * D_
                              + (size_t)m * D_ + n0 + w4 * 32;
            asm volatile("prefetch.global.L2 [%0];" :: "l"(pa));
        }
    }

    // ---------- fused epilogue: acc -> smem, then + mlp term + cbase -> out --
    cp_wait0();
    __syncthreads();                       // all frag reads done; reuse smem
    float* ftile = (float*)smem;           // 128 x FT_STRIDE fp32

    const int wn = (wid >> 2) * 64;
    const int r0l = wm + (lane >> 2);
    const int c0l = wn + (lane & 3) * 2;
#pragma unroll
    for (int im = 0; im < 2; im++) {
        const int r = r0l + im * 16;
#pragma unroll
        for (int nb = 0; nb < 8; nb++) {
            const int c = c0l + nb * 8;
            float2* q0 = (float2*)&ftile[r * FT_STRIDE + c];
            float2* q1 = (float2*)&ftile[(r + 8) * FT_STRIDE + c];
            *q0 = make_float2(acc[im][nb][0], acc[im][nb][1]);
            *q1 = make_float2(acc[im][nb][2], acc[im][nb][3]);
        }
    }
    __syncthreads();

    float mm[MS_];
#pragma unroll
    for (int m = 0; m < MS_; m++) mm[m] = __ldg(mlp_mask + b * MS_ + m);

    // 128 rows x 32 float4-cols, 256 threads -> 16 iters
#pragma unroll 2
    for (int i = tid; i < BM * (BN / 4); i += NTHREADS) {
        const int r = i >> 5;
        const int c = (i & 31) * 4;
        float4 v = *(const float4*)&ftile[r * FT_STRIDE + c];
        const float4 cb = *(const float4*)(&g_cbase[b * D_ + n0 + c]);
        v.x += cb.x; v.y += cb.y; v.z += cb.z; v.w += cb.w;
        const float* src = mlp_cache + (size_t)(row0 + r) * MS_ * D_ + n0 + c;
#pragma unroll
        for (int m = 0; m < MS_; m++) {
            const float4 u = *(const float4*)(src + (size_t)m * D_);
            v.x += mm[m] * u.x; v.y += mm[m] * u.y;
            v.z += mm[m] * u.z; v.w += mm[m] * u.w;
        }
        *(float4*)(out + (size_t)(row0 + r) * D_ + n0 + c) = v;
    }
}

// ---------------- launch ----------------
extern "C" void kernel_launch(void* const* d_in, const int* in_sizes, int n_in,
                              void* d_out, int out_size) {
    const float* mlp_cache  = (const float*)d_in[0];
    const float* attn_cache = (const float*)d_in[1];
    const float* mlp_mask   = (const float*)d_in[2];
    const float* attn_mask  = (const float*)d_in[3];
    const float* mlp_const  = (const float*)d_in[4];
    const float* attn_const = (const float*)d_in[5];
    const float* W_O        = (const float*)d_in[6];
    const float* post_bias  = (const float*)d_in[7];
    float* out = (float*)d_out;

    cudaFuncSetAttribute(gemm_kernel, cudaFuncAttributeMaxDynamicSharedMemorySize, SMEM_BYTES);

    prep_kernel<<<NA_BLK + NW_BLK + NC_BLK, 256>>>(attn_cache, attn_mask, W_O,
                                                   mlp_mask, mlp_const,
                                                   attn_const, post_bias);
    gemm_kernel<<<dim3(D_ / BN, BP_ / BM), NTHREADS, SMEM_BYTES>>>(mlp_cache,
                                                                   mlp_mask, out);
}